// round 1
// baseline (speedup 1.0000x reference)
#include <cuda_runtime.h>

#define GRIDN 256

// Per-dimension bracket: replicates jnp.searchsorted(p, x, side='right') with
// the reference's clamping and distance logic, for a monotone axis held in smem.
__device__ __forceinline__ void bracket(const float* __restrict__ p, float x,
                                        int& il, int& ir, float& dl, float& dr)
{
    // Analytic first guess for a ~uniform [0,1] linspace axis; fix-up loops make
    // it exact for any monotone axis (each runs at most ~1 iteration here).
    int g = (int)floorf(x * (float)(GRIDN - 1)) + 1;
    g = max(0, min(g, GRIDN));
    while (g < GRIDN && p[g] <= x) g++;
    while (g > 0 && p[g - 1] > x) g--;
    // g == searchsorted right. Clamp as reference does.
    ir = min(g, GRIDN - 1);
    il = max(ir - 1, 0);
    dl = fmaxf(x - p[il], 0.0f);
    dr = fmaxf(p[ir] - x, 0.0f);
    if (dl == 0.0f && dr == 0.0f) { dl = 1.0f; dr = 1.0f; }
}

__global__ __launch_bounds__(256)
void rgi_kernel(const float* __restrict__ x0, const float* __restrict__ x1,
                const float* __restrict__ x2,
                const float* __restrict__ p0, const float* __restrict__ p1,
                const float* __restrict__ p2,
                const float* __restrict__ values,
                float* __restrict__ out, int n)
{
    __shared__ float sp0[GRIDN], sp1[GRIDN], sp2[GRIDN];
    int tid = threadIdx.x;
    // blockDim.x == 256 == GRIDN: one coalesced load per axis.
    sp0[tid] = p0[tid];
    sp1[tid] = p1[tid];
    sp2[tid] = p2[tid];
    __syncthreads();

    int i = blockIdx.x * blockDim.x + tid;
    if (i >= n) return;

    float q0 = x0[i];
    float q1 = x1[i];
    float q2 = x2[i];

    int il0, ir0, il1, ir1, il2, ir2;
    float dl0, dr0, dl1, dr1, dl2, dr2;
    bracket(sp0, q0, il0, ir0, dl0, dr0);
    bracket(sp1, q1, il1, ir1, dl1, dr1);
    bracket(sp2, q2, il2, ir2, dl2, dr2);

    // Row bases for the 4 (i0,i1) combinations; corner loads issued together
    // so the 8 L2 accesses overlap (MLP=8).
    const long bll = ((long)il0 * GRIDN + il1) * GRIDN;
    const long blr = ((long)il0 * GRIDN + ir1) * GRIDN;
    const long brl = ((long)ir0 * GRIDN + il1) * GRIDN;
    const long brr = ((long)ir0 * GRIDN + ir1) * GRIDN;

    float v000 = __ldg(values + bll + il2);
    float v001 = __ldg(values + bll + ir2);
    float v010 = __ldg(values + blr + il2);
    float v011 = __ldg(values + blr + ir2);
    float v100 = __ldg(values + brl + il2);
    float v101 = __ldg(values + brl + ir2);
    float v110 = __ldg(values + brr + il2);
    float v111 = __ldg(values + brr + ir2);

    // Corner weight = product of OPPOSITE-side distances (reference semantics).
    float num = 0.0f;
    num = fmaf(v000, dr0 * dr1 * dr2, num);
    num = fmaf(v001, dr0 * dr1 * dl2, num);
    num = fmaf(v010, dr0 * dl1 * dr2, num);
    num = fmaf(v011, dr0 * dl1 * dl2, num);
    num = fmaf(v100, dl0 * dr1 * dr2, num);
    num = fmaf(v101, dl0 * dr1 * dl2, num);
    num = fmaf(v110, dl0 * dl1 * dr2, num);
    num = fmaf(v111, dl0 * dl1 * dl2, num);

    float denom = (dl0 + dr0) * (dl1 + dr1) * (dl2 + dr2);
    out[i] = num / denom;
}

extern "C" void kernel_launch(void* const* d_in, const int* in_sizes, int n_in,
                              void* d_out, int out_size)
{
    const float* x0 = (const float*)d_in[0];
    const float* x1 = (const float*)d_in[1];
    const float* x2 = (const float*)d_in[2];
    const float* p0 = (const float*)d_in[3];
    const float* p1 = (const float*)d_in[4];
    const float* p2 = (const float*)d_in[5];
    const float* values = (const float*)d_in[6];
    float* out = (float*)d_out;

    int n = in_sizes[0];
    int threads = 256;
    int blocks = (n + threads - 1) / threads;
    rgi_kernel<<<blocks, threads>>>(x0, x1, x2, p0, p1, p2, values, out, n);
}